// round 4
// baseline (speedup 1.0000x reference)
#include <cuda_runtime.h>

// Cumulative accumulators: [0]=sum(d^2), [1..5]=T0..T4 (sum d over valid & t>=qk),
// [6..10]=C0..C4 (count of valid & t>=qk). Bin j = cum[j] - cum[j+1].
__device__ double g_acc[11];
__device__ unsigned int g_ticket;

#define BLOCKS_PER_SM 6
#define GRID (148 * BLOCKS_PER_SM)   // one full wave
#define TPB  256

__global__ void __launch_bounds__(TPB, BLOCKS_PER_SM)
fused_loss_kernel(const float* __restrict__ y_pred,
                  const float* __restrict__ y_true,
                  const float* __restrict__ quants,
                  float* __restrict__ out, int n)
{
    const float q0 = quants[0], q1 = quants[1], q2 = quants[2];
    const float q3 = quants[3], q4 = quants[4], q5 = quants[5];

    float mse = 0.0f;
    // cumulative sums (fma pipe) and counts (split fma/alu for pipe balance)
    float T0 = 0, T1 = 0, T2 = 0, T3 = 0, T4 = 0;
    float c0f = 0, c1f = 0;
    int   c2i = 0, c3i = 0, c4i = 0;

    const int stride = GRID * TPB;
    const int tid    = blockIdx.x * TPB + threadIdx.x;
    const int n4     = n >> 2;
    const float4* __restrict__ p4 = (const float4*)y_pred;
    const float4* __restrict__ t4 = (const float4*)y_true;

// hi = (t <= q5); valid = (t >= q0) & hi; pk = (t >= qk) & hi.
// All predicates are AND-fused FSETPs (6 per element).
#define PR(p_, t_)                                  \
    do {                                            \
        float t = (t_);                             \
        float d = (p_)-t;                           \
        mse = fmaf(d, d, mse);                      \
        bool hi = (t <= q5);                        \
        bool v0 = (t >= q0) & hi;                   \
        bool v1 = (t >= q1) & hi;                   \
        bool v2 = (t >= q2) & hi;                   \
        bool v3 = (t >= q3) & hi;                   \
        bool v4 = (t >= q4) & hi;                   \
        if (v0) { T0 += d; c0f += 1.0f; }           \
        if (v1) { T1 += d; c1f += 1.0f; }           \
        if (v2) { T2 += d; c2i += 1; }              \
        if (v3) { T3 += d; c3i += 1; }              \
        if (v4) { T4 += d; c4i += 1; }              \
    } while (0)

    int i = tid;
    // two float4-pairs per iteration: 4 front-loaded LDG.128 (MLP=4)
    for (; i + stride < n4; i += 2 * stride) {
        float4 pa = p4[i];
        float4 pb = p4[i + stride];
        float4 ta = t4[i];
        float4 tb = t4[i + stride];
        PR(pa.x, ta.x); PR(pa.y, ta.y); PR(pa.z, ta.z); PR(pa.w, ta.w);
        PR(pb.x, tb.x); PR(pb.y, tb.y); PR(pb.z, tb.z); PR(pb.w, tb.w);
    }
    for (; i < n4; i += stride) {
        float4 pa = p4[i];
        float4 ta = t4[i];
        PR(pa.x, ta.x); PR(pa.y, ta.y); PR(pa.z, ta.z); PR(pa.w, ta.w);
    }
    for (int j = (n4 << 2) + tid; j < n; j += stride) {
        float p = y_pred[j];
        float t = y_true[j];
        PR(p, t);
    }
#undef PR

    // ---- block reduction of 11 partials ----
    float v[11] = {mse, T0, T1, T2, T3, T4,
                   c0f, c1f, (float)c2i, (float)c3i, (float)c4i};
#pragma unroll
    for (int k = 0; k < 11; k++) {
#pragma unroll
        for (int off = 16; off > 0; off >>= 1)
            v[k] += __shfl_down_sync(0xFFFFFFFFu, v[k], off);
    }

    __shared__ float sh[TPB / 32][11];
    const int wid = threadIdx.x >> 5;
    const int lid = threadIdx.x & 31;
    if (lid == 0) {
#pragma unroll
        for (int k = 0; k < 11; k++) sh[wid][k] = v[k];
    }
    __syncthreads();

    if (threadIdx.x < 11) {
        float acc = 0.0f;
#pragma unroll
        for (int w = 0; w < TPB / 32; w++) acc += sh[w][threadIdx.x];
        atomicAdd(&g_acc[threadIdx.x], (double)acc);
    }

    // ---- last block finalizes and resets (graph-replay safe) ----
    __syncthreads();
    if (threadIdx.x == 0) {
        __threadfence();
        unsigned int ticket = atomicAdd(&g_ticket, 1u);
        if (ticket == GRID - 1) {
            double A[11];
#pragma unroll
            for (int k = 0; k < 11; k++) A[k] = atomicAdd(&g_acc[k], 0.0);

            double mse_d = A[0] / (double)n;
            double m = 0.0;
#pragma unroll
            for (int j = 0; j < 5; j++) {
                double s = A[1 + j] - ((j < 4) ? A[2 + j] : 0.0);   // T_j - T_{j+1}
                double c = A[6 + j] - ((j < 4) ? A[7 + j] : 0.0);   // C_j - C_{j+1}
                double b = s / fmax(c, 1.0);
                double b2 = (c > 0.0) ? b * b : 0.0;
                m = fmax(m, b2);
            }
            m = fmax(m, 0.0);
            out[0] = (float)(mse_d + 5.0 * m);

#pragma unroll
            for (int k = 0; k < 11; k++) g_acc[k] = 0.0;
            __threadfence();
            g_ticket = 0u;
        }
    }
}

extern "C" void kernel_launch(void* const* d_in, const int* in_sizes, int n_in,
                              void* d_out, int out_size) {
    const float* y_pred = (const float*)d_in[0];
    const float* y_true = (const float*)d_in[1];
    const float* quants = (const float*)d_in[2];
    float* out = (float*)d_out;
    const int n = in_sizes[0];

    fused_loss_kernel<<<GRID, TPB>>>(y_pred, y_true, quants, out, n);
}

// round 5
// speedup vs baseline: 1.0072x; 1.0072x over previous
#include <cuda_runtime.h>
#include <cstdint>

// Cumulative accumulators: [0]=sum(d^2), [1..5]=T0..T4, [6..10]=C0..C4
__device__ double g_acc[11];
__device__ unsigned int g_ticket;

#define BLOCKS_PER_SM 5
#define GRID (148 * BLOCKS_PER_SM)
#define TPB  256
#define STAGE_ELEMS 2048
#define STAGE_BYTES (STAGE_ELEMS * 4)
#define NSTAGE 2

#define MBARRIER_INIT(addr, count) \
    asm volatile("mbarrier.init.shared.b64 [%0], %1;" :: "r"(addr), "r"(count) : "memory")

#define MBARRIER_EXPECT_TX(addr, bytes) \
    asm volatile("mbarrier.arrive.expect_tx.shared.b64 _, [%0], %1;" :: "r"(addr), "r"(bytes) : "memory")

#define BULK_G2S(dst_smem, src_gmem, bytes, mbar) \
    asm volatile("cp.async.bulk.shared::cluster.global.mbarrier::complete_tx::bytes [%0], [%1], %2, [%3];" \
                 :: "r"(dst_smem), "l"(src_gmem), "r"(bytes), "r"(mbar) : "memory")

#define MBARRIER_WAIT_PARITY(addr, parity) do {                                   \
    uint32_t _mbar = (addr);                                                      \
    uint32_t _par  = (parity);                                                    \
    asm volatile(                                                                 \
        "{\n\t"                                                                   \
        ".reg .pred P1;\n\t"                                                      \
        "WAIT_LOOP_%=:\n\t"                                                       \
        "mbarrier.try_wait.parity.shared.b64 P1, [%0], %1;\n\t"                   \
        "@P1 bra.uni WAIT_DONE_%=;\n\t"                                           \
        "bra.uni WAIT_LOOP_%=;\n\t"                                               \
        "WAIT_DONE_%=:\n\t"                                                       \
        "}"                                                                       \
        :: "r"(_mbar), "r"(_par) : "memory");                                     \
} while (0)

__global__ void __launch_bounds__(TPB, BLOCKS_PER_SM)
fused_loss_kernel(const float* __restrict__ y_pred,
                  const float* __restrict__ y_true,
                  const float* __restrict__ quants,
                  float* __restrict__ out, int n)
{
    __shared__ alignas(16) float sp[NSTAGE][STAGE_ELEMS];
    __shared__ alignas(16) float st[NSTAGE][STAGE_ELEMS];
    __shared__ alignas(8)  unsigned long long mbar[NSTAGE];
    __shared__ float shred[TPB / 32][11];

    const float q0 = quants[0], q1 = quants[1], q2 = quants[2];
    const float q3 = quants[3], q4 = quants[4], q5 = quants[5];

    float mse = 0.0f;
    float T0 = 0, T1 = 0, T2 = 0, T3 = 0, T4 = 0;
    float c0f = 0, c1f = 0;
    int   c2i = 0, c3i = 0, c4i = 0;

    const int tid = threadIdx.x;
    const int bid = blockIdx.x;

    const uint32_t mb0 = (uint32_t)__cvta_generic_to_shared(&mbar[0]);
    const uint32_t mb1 = (uint32_t)__cvta_generic_to_shared(&mbar[1]);

    const int stages_total = n / STAGE_ELEMS;
    int nst = (bid < stages_total) ? (stages_total - bid + GRID - 1) / GRID : 0;

    if (tid == 0) {
        MBARRIER_INIT(mb0, 1);
        MBARRIER_INIT(mb1, 1);
    }
    __syncthreads();

    // prologue: fill both slots
    if (tid == 0) {
#pragma unroll
        for (int j = 0; j < NSTAGE; j++) {
            if (j < nst) {
                size_t off = ((size_t)bid + (size_t)j * GRID) * STAGE_ELEMS;
                uint32_t mb = j ? mb1 : mb0;
                MBARRIER_EXPECT_TX(mb, 2 * STAGE_BYTES);
                BULK_G2S((uint32_t)__cvta_generic_to_shared(&sp[j][0]), y_pred + off, STAGE_BYTES, mb);
                BULK_G2S((uint32_t)__cvta_generic_to_shared(&st[j][0]), y_true + off, STAGE_BYTES, mb);
            }
        }
    }

// cumulative binning (exact searchsorted-right semantics; closed last bin via hi)
#define PR(p_, t_)                                  \
    do {                                            \
        float t = (t_);                             \
        float d = (p_)-t;                           \
        mse = fmaf(d, d, mse);                      \
        bool hi = (t <= q5);                        \
        bool v0 = (t >= q0) & hi;                   \
        bool v1 = (t >= q1) & hi;                   \
        bool v2 = (t >= q2) & hi;                   \
        bool v3 = (t >= q3) & hi;                   \
        bool v4 = (t >= q4) & hi;                   \
        if (v0) { T0 += d; c0f += 1.0f; }           \
        if (v1) { T1 += d; c1f += 1.0f; }           \
        if (v2) { T2 += d; c2i += 1; }              \
        if (v3) { T3 += d; c3i += 1; }              \
        if (v4) { T4 += d; c4i += 1; }              \
    } while (0)

    for (int j = 0; j < nst; j++) {
        const int slot   = j & 1;
        const int parity = (j >> 1) & 1;
        const uint32_t mb = slot ? mb1 : mb0;
        MBARRIER_WAIT_PARITY(mb, parity);

        const float4* __restrict__ pp = (const float4*)&sp[slot][0];
        const float4* __restrict__ tt = (const float4*)&st[slot][0];
        float4 pa = pp[tid];
        float4 pb = pp[tid + TPB];
        float4 ta = tt[tid];
        float4 tb = tt[tid + TPB];
        PR(pa.x, ta.x); PR(pa.y, ta.y); PR(pa.z, ta.z); PR(pa.w, ta.w);
        PR(pb.x, tb.x); PR(pb.y, tb.y); PR(pb.z, tb.z); PR(pb.w, tb.w);

        __syncthreads();   // everyone done reading this slot

        if (tid == 0 && (j + NSTAGE) < nst) {
            size_t off = ((size_t)bid + (size_t)(j + NSTAGE) * GRID) * STAGE_ELEMS;
            MBARRIER_EXPECT_TX(mb, 2 * STAGE_BYTES);
            BULK_G2S((uint32_t)__cvta_generic_to_shared(&sp[slot][0]), y_pred + off, STAGE_BYTES, mb);
            BULK_G2S((uint32_t)__cvta_generic_to_shared(&st[slot][0]), y_true + off, STAGE_BYTES, mb);
        }
    }

    // tail: elements not covered by full stages (n % STAGE_ELEMS)
    for (int j = stages_total * STAGE_ELEMS + bid * TPB + tid; j < n; j += GRID * TPB) {
        float p = y_pred[j];
        float t = y_true[j];
        PR(p, t);
    }
#undef PR

    // ---- block reduction of 11 partials ----
    float v[11] = {mse, T0, T1, T2, T3, T4,
                   c0f, c1f, (float)c2i, (float)c3i, (float)c4i};
#pragma unroll
    for (int k = 0; k < 11; k++) {
#pragma unroll
        for (int off = 16; off > 0; off >>= 1)
            v[k] += __shfl_down_sync(0xFFFFFFFFu, v[k], off);
    }

    const int wid = tid >> 5;
    const int lid = tid & 31;
    if (lid == 0) {
#pragma unroll
        for (int k = 0; k < 11; k++) shred[wid][k] = v[k];
    }
    __syncthreads();

    if (tid < 11) {
        float acc = 0.0f;
#pragma unroll
        for (int w = 0; w < TPB / 32; w++) acc += shred[w][tid];
        atomicAdd(&g_acc[tid], (double)acc);
    }

    // ---- last block finalizes and resets (graph-replay safe) ----
    __syncthreads();
    if (tid == 0) {
        __threadfence();
        unsigned int ticket = atomicAdd(&g_ticket, 1u);
        if (ticket == GRID - 1) {
            double A[11];
#pragma unroll
            for (int k = 0; k < 11; k++) A[k] = atomicAdd(&g_acc[k], 0.0);

            double mse_d = A[0] / (double)n;
            double m = 0.0;
#pragma unroll
            for (int j = 0; j < 5; j++) {
                double s = A[1 + j] - ((j < 4) ? A[2 + j] : 0.0);   // T_j - T_{j+1}
                double c = A[6 + j] - ((j < 4) ? A[7 + j] : 0.0);   // C_j - C_{j+1}
                double b = s / fmax(c, 1.0);
                double b2 = (c > 0.0) ? b * b : 0.0;
                m = fmax(m, b2);
            }
            m = fmax(m, 0.0);
            out[0] = (float)(mse_d + 5.0 * m);

#pragma unroll
            for (int k = 0; k < 11; k++) g_acc[k] = 0.0;
            __threadfence();
            g_ticket = 0u;
        }
    }
}

extern "C" void kernel_launch(void* const* d_in, const int* in_sizes, int n_in,
                              void* d_out, int out_size) {
    const float* y_pred = (const float*)d_in[0];
    const float* y_true = (const float*)d_in[1];
    const float* quants = (const float*)d_in[2];
    float* out = (float*)d_out;
    const int n = in_sizes[0];

    fused_loss_kernel<<<GRID, TPB>>>(y_pred, y_true, quants, out, n);
}